// round 5
// baseline (speedup 1.0000x reference)
#include <cuda_runtime.h>

// SymbolSubcarrierAutocorrelation:
//   per (n, a): 5x33 complex tile T.
//   X  = F_sym @ T @ F_sub            (2D unitary DFT)
//   P  = |X|^2                        (real)
//   Y  = F_sym^H @ P @ F_sub^H        (inverse 2D DFT, W-side first on REAL P)
//
// Output-format adaptive: out_size == C (complex count)  -> real part, float32
//                         out_size >= 2C                 -> interleaved float2
// Every global access bounded by harness-provided sizes.

#define SDIM 5
#define WDIM 33
#define ADIM 16
#define TILES_PER_BLOCK 8
#define THREADS (TILES_PER_BLOCK * WDIM)   // 264

__global__ __launch_bounds__(THREADS)
void autocorr_kernel(const float* __restrict__ xr, const float* __restrict__ xi,
                     const float* __restrict__ fsA, const float* __restrict__ fsB,
                     const float* __restrict__ fwA, const float* __restrict__ fwB,
                     float* __restrict__ outf,
                     int total_tiles,
                     unsigned int xcount,        // element count of each x array
                     unsigned int out_limit,     // out_size as given (conservative float units)
                     int real_only)              // 1: write real part only; 0: interleaved float2
{
    __shared__ float2 sFsub[WDIM * WDIM];                 // 8712 B
    __shared__ float2 sFsym[SDIM * SDIM];                 //  200 B
    __shared__ float2 sT1[TILES_PER_BLOCK][SDIM * WDIM];  // 10560 B
    __shared__ float  sP [TILES_PER_BLOCK][SDIM * WDIM];  //  5280 B

    const int tid = threadIdx.x;

    // Orientation detect: unitary DFT real[0][0] = 1/sqrt(n) (>0.17), imag[0][0] = 0.
    const bool swSub = (fabsf(fwA[0]) < 1e-3f);
    const bool swSym = (fabsf(fsA[0]) < 1e-3f);
    const float* __restrict__ fwr = swSub ? fwB : fwA;
    const float* __restrict__ fwi = swSub ? fwA : fwB;
    const float* __restrict__ fsr = swSym ? fsB : fsA;
    const float* __restrict__ fsi = swSym ? fsA : fsB;

    for (int i = tid; i < WDIM * WDIM; i += THREADS)
        sFsub[i] = make_float2(fwr[i], fwi[i]);
    if (tid < SDIM * SDIM)
        sFsym[tid] = make_float2(fsr[tid], fsi[tid]);
    __syncthreads();

    const int tb = tid / WDIM;          // tile slot in block
    const int v  = tid - tb * WDIM;     // 0..32 (output subcarrier column)
    int tile = blockIdx.x * TILES_PER_BLOCK + tb;
    if (tile >= total_tiles) tile = 0;  // benign duplicate work on tail
    const int n = tile >> 4;            // ADIM == 16
    const int a = tile & 15;

    // ---- Stage 1: T1[s][v] = sum_t F_sym[s][t] * x[n,t,a,v] ----
    float2 xc[SDIM];
    #pragma unroll
    for (int t = 0; t < SDIM; t++) {
        unsigned int idx = (((unsigned int)n * SDIM + t) * ADIM + a) * WDIM + v;
        if (idx >= xcount) idx = 0;     // insurance
        xc[t] = make_float2(xr[idx], xi[idx]);
    }
    #pragma unroll
    for (int s = 0; s < SDIM; s++) {
        float ar = 0.f, ai = 0.f;
        #pragma unroll
        for (int t = 0; t < SDIM; t++) {
            float2 f = sFsym[s * SDIM + t];
            ar += f.x * xc[t].x - f.y * xc[t].y;
            ai += f.x * xc[t].y + f.y * xc[t].x;
        }
        sT1[tb][s * WDIM + v] = make_float2(ar, ai);
    }
    __syncthreads();

    // ---- Stage 2: X[s][v] = sum_w T1[s][w] * F_sub[w][v]; then P = |X|^2 ----
    {
        float accr[SDIM] = {0.f, 0.f, 0.f, 0.f, 0.f};
        float acci[SDIM] = {0.f, 0.f, 0.f, 0.f, 0.f};
        #pragma unroll 3
        for (int w = 0; w < WDIM; w++) {
            float2 f = sFsub[w * WDIM + v];          // per-thread, conflict-free
            #pragma unroll
            for (int s = 0; s < SDIM; s++) {
                float2 t1 = sT1[tb][s * WDIM + w];   // warp broadcast
                accr[s] += t1.x * f.x - t1.y * f.y;
                acci[s] += t1.x * f.y + t1.y * f.x;
            }
        }
        #pragma unroll
        for (int s = 0; s < SDIM; s++)
            sP[tb][s * WDIM + v] = accr[s] * accr[s] + acci[s] * acci[s];
    }
    __syncthreads();

    // ---- Stage 3: T2[s][v] = sum_w P[s][w] * conj(F_sub[w][v])  (P is REAL) ----
    float t2r[SDIM] = {0.f, 0.f, 0.f, 0.f, 0.f};
    float t2i[SDIM] = {0.f, 0.f, 0.f, 0.f, 0.f};
    #pragma unroll 3
    for (int w = 0; w < WDIM; w++) {
        float2 f = sFsub[w * WDIM + v];
        #pragma unroll
        for (int s = 0; s < SDIM; s++) {
            float p = sP[tb][s * WDIM + w];          // warp broadcast
            t2r[s] += p * f.x;
            t2i[s] -= p * f.y;
        }
    }

    // ---- Stage 4: Y[sp][v] = sum_s conj(F_sym[s][sp]) * T2[s][v]; store ----
    #pragma unroll
    for (int sp = 0; sp < SDIM; sp++) {
        float yr = 0.f, yi = 0.f;
        #pragma unroll
        for (int s = 0; s < SDIM; s++) {
            float2 f = sFsym[s * SDIM + sp];
            yr += f.x * t2r[s] + f.y * t2i[s];
            yi += f.x * t2i[s] - f.y * t2r[s];
        }
        unsigned int oidx = (((unsigned int)n * SDIM + sp) * ADIM + a) * WDIM + v;
        if (real_only) {
            if (oidx < out_limit)
                outf[oidx] = yr;
        } else {
            if (2u * oidx + 1u < out_limit)
                reinterpret_cast<float2*>(outf)[oidx] = make_float2(yr, yi);
        }
    }
}

extern "C" void kernel_launch(void* const* d_in, const int* in_sizes, int n_in,
                              void* d_out, int out_size)
{
    // Bind by element count (25 -> F_sym pair, 1089 -> F_sub pair, largest -> x pair).
    long long big_raw = -1;
    for (int i = 0; i < n_in; i++)
        if ((long long)in_sizes[i] > big_raw) big_raw = in_sizes[i];

    const float *xr = 0, *xi = 0, *fsA = 0, *fsB = 0, *fwA = 0, *fwB = 0;
    int nsym = 0, nsub = 0, nbig = 0;
    for (int i = 0; i < n_in; i++) {
        const float* p = (const float*)d_in[i];
        long long c = in_sizes[i];
        if (c == SDIM * SDIM) {
            if (nsym++ == 0) fsA = p; else if (!fsB) fsB = p;
        } else if (c == WDIM * WDIM) {
            if (nsub++ == 0) fwA = p; else if (!fwB) fwB = p;
        } else if (c == big_raw) {
            if (nbig++ == 0) xr = p; else if (!xi) xi = p;
        }
    }
    if (!xr || !xi || !fsA || !fsB || !fwA || !fwB) return;

    const long long C = big_raw;                    // complex output count == x element count
    const int N = (int)(C / (SDIM * ADIM * WDIM));
    const int total_tiles = N * ADIM;
    if (total_tiles <= 0) return;
    const int blocks = (total_tiles + TILES_PER_BLOCK - 1) / TILES_PER_BLOCK;

    // Output format: out_size >= 2C -> interleaved complex floats; else real part only.
    const int real_only = ((long long)out_size >= 2 * C) ? 0 : 1;

    autocorr_kernel<<<blocks, THREADS>>>(
        xr, xi, fsA, fsB, fwA, fwB, (float*)d_out, total_tiles,
        (unsigned int)C, (unsigned int)out_size, real_only);
}

// round 6
// speedup vs baseline: 1.1910x; 1.1910x over previous
#include <cuda_runtime.h>

// SymbolSubcarrierAutocorrelation — Round 6.
//   X = F_sym @ T @ F_sub ; P = |X|^2 ; Y = F_sym^H @ P @ F_sub^H
// Optimizations this round:
//   * SoA F_sub in smem (conflict-free stride-1 LDS.32)
//   * T1 packed as 3x float4 rows, P as float4+float (vector broadcasts)
//   * Hermitian folding: Y[(-sp)%5][(-v)%33] = conj(Y[sp][v]) since P is real;
//     stages 3-4 computed only for v=0..16, repacked onto threads 0..135 so
//     whole warps idle (true issue savings); mirrors written by conjugation.

#define SDIM 5
#define WDIM 33
#define ADIM 16
#define TPB 8
#define THREADS (TPB * WDIM)   // 264
#define HALFW 17               // columns 0..16 computed directly

__global__ __launch_bounds__(THREADS)
void autocorr_kernel(const float* __restrict__ xr, const float* __restrict__ xi,
                     const float* __restrict__ fsA, const float* __restrict__ fsB,
                     const float* __restrict__ fwA, const float* __restrict__ fwB,
                     float* __restrict__ outf,
                     int total_tiles,
                     unsigned int xcount,
                     unsigned int out_limit,
                     int real_only)
{
    __shared__ float  sFr[WDIM * WDIM];          // F_sub real (SoA)
    __shared__ float  sFi[WDIM * WDIM];          // F_sub imag
    __shared__ float2 sFsym[SDIM * SDIM];
    __shared__ float4 sT14[TPB][3][WDIM];        // (re0,im0,re1,im1)(re2,im2,re3,im3)(re4,im4,-,-)
    __shared__ float4 sPa[TPB][WDIM];            // P[0..3]
    __shared__ float  sPb[TPB][WDIM];            // P[4]

    const int tid = threadIdx.x;

    // Orientation detect: unitary DFT real[0][0]=1/sqrt(n)>0.17, imag[0][0]=0.
    const bool swSub = (fabsf(fwA[0]) < 1e-3f);
    const bool swSym = (fabsf(fsA[0]) < 1e-3f);
    const float* __restrict__ fwr = swSub ? fwB : fwA;
    const float* __restrict__ fwi = swSub ? fwA : fwB;
    const float* __restrict__ fsr = swSym ? fsB : fsA;
    const float* __restrict__ fsi = swSym ? fsA : fsB;

    for (int i = tid; i < WDIM * WDIM; i += THREADS) {
        sFr[i] = fwr[i];
        sFi[i] = fwi[i];
    }
    if (tid < SDIM * SDIM)
        sFsym[tid] = make_float2(fsr[tid], fsi[tid]);
    __syncthreads();

    const int tb = tid / WDIM;
    const int v  = tid - tb * WDIM;
    int tile = blockIdx.x * TPB + tb;
    if (tile >= total_tiles) tile = 0;
    const int n = tile >> 4;      // ADIM == 16
    const int a = tile & 15;

    // ---- Stage 1: T1[s][v] = sum_t F_sym[s][t] * x[n,t,a,v] ----
    {
        float2 xc[SDIM];
        #pragma unroll
        for (int t = 0; t < SDIM; t++) {
            unsigned int idx = (((unsigned int)n * SDIM + t) * ADIM + a) * WDIM + v;
            if (idx >= xcount) idx = 0;
            xc[t] = make_float2(xr[idx], xi[idx]);
        }
        float t1r[SDIM], t1i[SDIM];
        #pragma unroll
        for (int s = 0; s < SDIM; s++) {
            float ar = 0.f, ai = 0.f;
            #pragma unroll
            for (int t = 0; t < SDIM; t++) {
                float2 f = sFsym[s * SDIM + t];
                ar += f.x * xc[t].x - f.y * xc[t].y;
                ai += f.x * xc[t].y + f.y * xc[t].x;
            }
            t1r[s] = ar; t1i[s] = ai;
        }
        sT14[tb][0][v] = make_float4(t1r[0], t1i[0], t1r[1], t1i[1]);
        sT14[tb][1][v] = make_float4(t1r[2], t1i[2], t1r[3], t1i[3]);
        sT14[tb][2][v] = make_float4(t1r[4], t1i[4], 0.f, 0.f);
    }
    __syncthreads();

    // ---- Stage 2: X[s][v] = sum_w T1[s][w] * F_sub[w][v]; P = |X|^2 ----
    {
        float accr[SDIM] = {0.f, 0.f, 0.f, 0.f, 0.f};
        float acci[SDIM] = {0.f, 0.f, 0.f, 0.f, 0.f};
        #pragma unroll 3
        for (int w = 0; w < WDIM; w++) {
            const float c  = sFr[w * WDIM + v];     // stride-1, conflict-free
            const float si = sFi[w * WDIM + v];
            const float4 A = sT14[tb][0][w];        // broadcast
            const float4 B = sT14[tb][1][w];
            const float4 C = sT14[tb][2][w];
            accr[0] += A.x * c - A.y * si;  acci[0] += A.x * si + A.y * c;
            accr[1] += A.z * c - A.w * si;  acci[1] += A.z * si + A.w * c;
            accr[2] += B.x * c - B.y * si;  acci[2] += B.x * si + B.y * c;
            accr[3] += B.z * c - B.w * si;  acci[3] += B.z * si + B.w * c;
            accr[4] += C.x * c - C.y * si;  acci[4] += C.x * si + C.y * c;
        }
        sPa[tb][v] = make_float4(accr[0]*accr[0] + acci[0]*acci[0],
                                 accr[1]*accr[1] + acci[1]*acci[1],
                                 accr[2]*accr[2] + acci[2]*acci[2],
                                 accr[3]*accr[3] + acci[3]*acci[3]);
        sPb[tb][v] = accr[4]*accr[4] + acci[4]*acci[4];
    }
    __syncthreads();

    // ---- Stages 3+4 on repacked threads: only columns 0..16, mirrors by conj ----
    const int u = tid;
    if (u < TPB * HALFW) {                 // 136 active threads -> whole warps idle
        const int tb2 = u / HALFW;
        const int vv  = u - tb2 * HALFW;
        int tile2 = blockIdx.x * TPB + tb2;
        if (tile2 >= total_tiles) tile2 = 0;
        const int n2 = tile2 >> 4;
        const int a2 = tile2 & 15;

        // Stage 3: T2[s][vv] = sum_w P[s][w] * conj(F_sub[w][vv])
        float t2r[SDIM] = {0.f, 0.f, 0.f, 0.f, 0.f};
        float t2i[SDIM] = {0.f, 0.f, 0.f, 0.f, 0.f};
        #pragma unroll 3
        for (int w = 0; w < WDIM; w++) {
            const float c  = sFr[w * WDIM + vv];
            const float si = sFi[w * WDIM + vv];
            const float4 Pa = sPa[tb2][w];         // broadcast
            const float  Pb = sPb[tb2][w];
            t2r[0] += Pa.x * c;  t2i[0] -= Pa.x * si;
            t2r[1] += Pa.y * c;  t2i[1] -= Pa.y * si;
            t2r[2] += Pa.z * c;  t2i[2] -= Pa.z * si;
            t2r[3] += Pa.w * c;  t2i[3] -= Pa.w * si;
            t2r[4] += Pb  * c;   t2i[4] -= Pb  * si;
        }

        // Stage 4: Y[sp][vv] = sum_s conj(F_sym[s][sp]) * T2[s][vv]
        #pragma unroll
        for (int sp = 0; sp < SDIM; sp++) {
            float yr = 0.f, yi = 0.f;
            #pragma unroll
            for (int s = 0; s < SDIM; s++) {
                float2 f = sFsym[s * SDIM + sp];
                yr += f.x * t2r[s] + f.y * t2i[s];
                yi += f.x * t2i[s] - f.y * t2r[s];
            }
            unsigned int oidx = (((unsigned int)n2 * SDIM + sp) * ADIM + a2) * WDIM + vv;
            if (real_only) {
                if (oidx < out_limit) outf[oidx] = yr;
            } else {
                if (2u * oidx + 1u < out_limit)
                    reinterpret_cast<float2*>(outf)[oidx] = make_float2(yr, yi);
            }
            // Mirror: Y[(5-sp)%5][33-vv] = conj(Y[sp][vv])  (vv=0 column is self-paired)
            if (vv > 0) {
                const int sp2 = (SDIM - sp) % SDIM;
                const int v2  = WDIM - vv;
                unsigned int midx = (((unsigned int)n2 * SDIM + sp2) * ADIM + a2) * WDIM + v2;
                if (real_only) {
                    if (midx < out_limit) outf[midx] = yr;
                } else {
                    if (2u * midx + 1u < out_limit)
                        reinterpret_cast<float2*>(outf)[midx] = make_float2(yr, -yi);
                }
            }
        }
    }
}

extern "C" void kernel_launch(void* const* d_in, const int* in_sizes, int n_in,
                              void* d_out, int out_size)
{
    long long big_raw = -1;
    for (int i = 0; i < n_in; i++)
        if ((long long)in_sizes[i] > big_raw) big_raw = in_sizes[i];

    const float *xr = 0, *xi = 0, *fsA = 0, *fsB = 0, *fwA = 0, *fwB = 0;
    int nsym = 0, nsub = 0, nbig = 0;
    for (int i = 0; i < n_in; i++) {
        const float* p = (const float*)d_in[i];
        long long c = in_sizes[i];
        if (c == SDIM * SDIM) {
            if (nsym++ == 0) fsA = p; else if (!fsB) fsB = p;
        } else if (c == WDIM * WDIM) {
            if (nsub++ == 0) fwA = p; else if (!fwB) fwB = p;
        } else if (c == big_raw) {
            if (nbig++ == 0) xr = p; else if (!xi) xi = p;
        }
    }
    if (!xr || !xi || !fsA || !fsB || !fwA || !fwB) return;

    const long long C = big_raw;
    const int N = (int)(C / (SDIM * ADIM * WDIM));
    const int total_tiles = N * ADIM;
    if (total_tiles <= 0) return;
    const int blocks = (total_tiles + TPB - 1) / TPB;

    const int real_only = ((long long)out_size >= 2 * C) ? 0 : 1;

    autocorr_kernel<<<blocks, THREADS>>>(
        xr, xi, fsA, fsB, fwA, fwB, (float*)d_out, total_tiles,
        (unsigned int)C, (unsigned int)out_size, real_only);
}

// round 7
// speedup vs baseline: 1.6406x; 1.3775x over previous
#include <cuda_runtime.h>

// SymbolSubcarrierAutocorrelation — Round 7: conjugate-pair folding everywhere.
// Thread = (tile, v) with v in [0,16]; each thread owns column pair (v, 33-v).
// F[33-w][v] = conj(F[w][v]) and F[w][33-v] = conj(F[w][v]) halve all 33-wide stages.

#define SDIM 5
#define WDIM 33
#define ADIM 16
#define HALFW 17              // v = 0..16 (v=0 self-paired)
#define NPAIR 16              // w-pairs 1..16
#define TPB 15                // tiles per block
#define THREADS (TPB * HALFW) // 255

__global__ __launch_bounds__(THREADS)
void autocorr_kernel(const float* __restrict__ xr, const float* __restrict__ xi,
                     const float* __restrict__ fsA, const float* __restrict__ fsB,
                     const float* __restrict__ fwA, const float* __restrict__ fwB,
                     float* __restrict__ outf,
                     int total_tiles,
                     unsigned int xcount,
                     unsigned int out_limit,
                     int real_only)
{
    __shared__ float  sFr[NPAIR * HALFW];       // F_sub rows 1..16, cols 0..16 (real)
    __shared__ float  sFi[NPAIR * HALFW];       // imag
    __shared__ float2 sFsym[SDIM * SDIM];
    __shared__ float4 sSD [TPB][NPAIR][SDIM];   // (Sr, Si, Dr, Di) per (pair, s)
    __shared__ float2 sT10[TPB][SDIM];          // T1[s][0]
    __shared__ float2 sED [TPB][NPAIR][SDIM];   // (E, D) per (pair, s)
    __shared__ float  sP0 [TPB][SDIM];          // P[s][0]

    const int tid = threadIdx.x;

    // Orientation detect: unitary DFT real[0][0]=1/sqrt(n)>0.17, imag[0][0]=0.
    const bool swSub = (fabsf(fwA[0]) < 1e-3f);
    const bool swSym = (fabsf(fsA[0]) < 1e-3f);
    const float* __restrict__ fwr = swSub ? fwB : fwA;
    const float* __restrict__ fwi = swSub ? fwA : fwB;
    const float* __restrict__ fsr = swSym ? fsB : fsA;
    const float* __restrict__ fsi = swSym ? fsA : fsB;

    const float k = fwr[0];                     // 1/sqrt(33): F_sub[0][*] == k (real)

    // Compact F_sub load: rows w=1..16, cols v=0..16.
    for (int i = tid; i < NPAIR * HALFW; i += THREADS) {
        const int w = i / HALFW + 1;
        const int c = i - (w - 1) * HALFW;
        sFr[i] = fwr[w * WDIM + c];
        sFi[i] = fwi[w * WDIM + c];
    }
    if (tid < SDIM * SDIM)
        sFsym[tid] = make_float2(fsr[tid], fsi[tid]);
    __syncthreads();

    const int ts = tid / HALFW;                 // tile slot 0..14
    const int v  = tid - ts * HALFW;            // 0..16
    int tile = blockIdx.x * TPB + ts;
    if (tile >= total_tiles) tile = 0;          // benign duplicate work on tail
    const int n = tile >> 4;                    // ADIM == 16
    const int a = tile & 15;
    const int vm = (v == 0) ? 0 : WDIM - v;     // mirror column

    // ---- Stage 1: T1[s] for columns v and vm; store Sigma/Delta (or T10) ----
    {
        float2 xa[SDIM], xb[SDIM];
        #pragma unroll
        for (int t = 0; t < SDIM; t++) {
            unsigned int base = (((unsigned int)n * SDIM + t) * ADIM + a) * WDIM;
            unsigned int iA = base + v;  if (iA >= xcount) iA = 0;
            unsigned int iB = base + vm; if (iB >= xcount) iB = 0;
            xa[t] = make_float2(xr[iA], xi[iA]);
            xb[t] = make_float2(xr[iB], xi[iB]);
        }
        #pragma unroll
        for (int s = 0; s < SDIM; s++) {
            float Ar = 0.f, Ai = 0.f, Br = 0.f, Bi = 0.f;
            #pragma unroll
            for (int t = 0; t < SDIM; t++) {
                float2 f = sFsym[s * SDIM + t];
                Ar += f.x * xa[t].x - f.y * xa[t].y;
                Ai += f.x * xa[t].y + f.y * xa[t].x;
                Br += f.x * xb[t].x - f.y * xb[t].y;
                Bi += f.x * xb[t].y + f.y * xb[t].x;
            }
            if (v == 0)
                sT10[ts][s] = make_float2(Ar, Ai);
            else
                sSD[ts][v - 1][s] = make_float4(Ar + Br, Ai + Bi, Ar - Br, Ai - Bi);
        }
    }
    __syncthreads();

    // ---- Stage 2: X[v], X[vm] via folded 33-pt DFT; then P, store (E,D) ----
    {
        float XrV[SDIM], XiV[SDIM], XrM[SDIM], XiM[SDIM];
        #pragma unroll
        for (int s = 0; s < SDIM; s++) {
            float2 t10 = sT10[ts][s];           // broadcast
            XrV[s] = k * t10.x;  XiV[s] = k * t10.y;
            XrM[s] = XrV[s];     XiM[s] = XiV[s];
        }
        #pragma unroll 4
        for (int w = 0; w < NPAIR; w++) {
            const float c  = sFr[w * HALFW + v];     // stride-1, conflict-free
            const float si = sFi[w * HALFW + v];
            #pragma unroll
            for (int s = 0; s < SDIM; s++) {
                const float4 sd = sSD[ts][w][s];     // broadcast
                XrV[s] += c * sd.x - si * sd.w;      // c*Sr - s*Di
                XiV[s] += c * sd.y + si * sd.z;      // c*Si + s*Dr
                XrM[s] += c * sd.x + si * sd.w;
                XiM[s] += c * sd.y - si * sd.z;
            }
        }
        #pragma unroll
        for (int s = 0; s < SDIM; s++) {
            const float Pv = XrV[s] * XrV[s] + XiV[s] * XiV[s];
            const float Pm = XrM[s] * XrM[s] + XiM[s] * XiM[s];
            if (v == 0)
                sP0[ts][s] = Pv;
            else
                sED[ts][v - 1][s] = make_float2(Pv + Pm, Pv - Pm);
        }
    }
    __syncthreads();

    // ---- Stage 3: T2[s][v] = sum_w P[s][w] * conj(F[w][v]), doubly folded ----
    float t2r[SDIM], t2i[SDIM];
    #pragma unroll
    for (int s = 0; s < SDIM; s++) {
        t2r[s] = k * sP0[ts][s];
        t2i[s] = 0.f;
    }
    #pragma unroll 4
    for (int w = 0; w < NPAIR; w++) {
        const float c  = sFr[w * HALFW + v];
        const float si = sFi[w * HALFW + v];
        #pragma unroll
        for (int s = 0; s < SDIM; s++) {
            const float2 ed = sED[ts][w][s];         // broadcast
            t2r[s] += ed.x * c;                      // E*c
            t2i[s] -= ed.y * si;                     // -D*s
        }
    }

    // ---- Stage 4: Y[sp][v] = sum_s conj(F_sym[s][sp]) * T2[s][v]; store + mirror ----
    #pragma unroll
    for (int sp = 0; sp < SDIM; sp++) {
        float yr = 0.f, yi = 0.f;
        #pragma unroll
        for (int s = 0; s < SDIM; s++) {
            float2 f = sFsym[s * SDIM + sp];
            yr += f.x * t2r[s] + f.y * t2i[s];
            yi += f.x * t2i[s] - f.y * t2r[s];
        }
        unsigned int oidx = (((unsigned int)n * SDIM + sp) * ADIM + a) * WDIM + v;
        if (real_only) {
            if (oidx < out_limit) outf[oidx] = yr;
        } else {
            if (2u * oidx + 1u < out_limit)
                reinterpret_cast<float2*>(outf)[oidx] = make_float2(yr, yi);
        }
        if (v > 0) {   // Hermitian mirror: Y[(5-sp)%5][33-v] = conj(Y[sp][v])
            const int sp2 = (SDIM - sp) % SDIM;
            unsigned int midx = (((unsigned int)n * SDIM + sp2) * ADIM + a) * WDIM + (WDIM - v);
            if (real_only) {
                if (midx < out_limit) outf[midx] = yr;
            } else {
                if (2u * midx + 1u < out_limit)
                    reinterpret_cast<float2*>(outf)[midx] = make_float2(yr, -yi);
            }
        }
    }
}

extern "C" void kernel_launch(void* const* d_in, const int* in_sizes, int n_in,
                              void* d_out, int out_size)
{
    long long big_raw = -1;
    for (int i = 0; i < n_in; i++)
        if ((long long)in_sizes[i] > big_raw) big_raw = in_sizes[i];

    const float *xr = 0, *xi = 0, *fsA = 0, *fsB = 0, *fwA = 0, *fwB = 0;
    int nsym = 0, nsub = 0, nbig = 0;
    for (int i = 0; i < n_in; i++) {
        const float* p = (const float*)d_in[i];
        long long c = in_sizes[i];
        if (c == SDIM * SDIM) {
            if (nsym++ == 0) fsA = p; else if (!fsB) fsB = p;
        } else if (c == WDIM * WDIM) {
            if (nsub++ == 0) fwA = p; else if (!fwB) fwB = p;
        } else if (c == big_raw) {
            if (nbig++ == 0) xr = p; else if (!xi) xi = p;
        }
    }
    if (!xr || !xi || !fsA || !fsB || !fwA || !fwB) return;

    const long long C = big_raw;
    const int N = (int)(C / (SDIM * ADIM * WDIM));
    const int total_tiles = N * ADIM;
    if (total_tiles <= 0) return;
    const int blocks = (total_tiles + TPB - 1) / TPB;

    const int real_only = ((long long)out_size >= 2 * C) ? 0 : 1;

    autocorr_kernel<<<blocks, THREADS>>>(
        xr, xi, fsA, fsB, fwA, fwB, (float*)d_out, total_tiles,
        (unsigned int)C, (unsigned int)out_size, real_only);
}

// round 8
// speedup vs baseline: 1.7500x; 1.0667x over previous
#include <cuda_runtime.h>

// SymbolSubcarrierAutocorrelation — Round 8: cut LDS instruction count.
//   * F_sym eliminated from smem: F_sym[s][t] = z[(s*t)%5], z in registers
//   * F_sub stored as interleaved float2 (c,s): 1 LDS.64 per (w,stage)
//   * (E,D) packed as float4+float4+float2: 3 LDS / 3 STS per w in stage 3
// Algebra identical to Round 7 (conjugate-pair folded, Hermitian mirror outputs).

#define SDIM 5
#define WDIM 33
#define ADIM 16
#define HALFW 17              // v = 0..16 (v=0 self-paired)
#define NPAIR 16              // w-pairs 1..16
#define TPB 15                // tiles per block
#define THREADS (TPB * HALFW) // 255

__global__ __launch_bounds__(THREADS)
void autocorr_kernel(const float* __restrict__ xr, const float* __restrict__ xi,
                     const float* __restrict__ fsA, const float* __restrict__ fsB,
                     const float* __restrict__ fwA, const float* __restrict__ fwB,
                     float* __restrict__ outf,
                     int total_tiles,
                     unsigned int xcount,
                     unsigned int out_limit,
                     int real_only)
{
    __shared__ float2 sFcs[NPAIR * HALFW];      // F_sub (re,im) rows 1..16, cols 0..16
    __shared__ float4 sSD [TPB][NPAIR][SDIM];   // (Sr, Si, Dr, Di) per (pair, s)
    __shared__ float2 sT10[TPB][SDIM];          // T1[s][0]
    __shared__ float4 sEDa[TPB][NPAIR];         // E0..E3
    __shared__ float4 sEDb[TPB][NPAIR];         // D0..D3
    __shared__ float2 sEDc[TPB][NPAIR];         // (E4, D4)
    __shared__ float  sP0 [TPB][SDIM];          // P[s][0]

    const int tid = threadIdx.x;

    // Orientation detect: unitary DFT real[0][0]=1/sqrt(n)>0.17, imag[0][0]=0.
    const bool swSub = (fabsf(fwA[0]) < 1e-3f);
    const bool swSym = (fabsf(fsA[0]) < 1e-3f);
    const float* __restrict__ fwr = swSub ? fwB : fwA;
    const float* __restrict__ fwi = swSub ? fwA : fwB;
    const float* __restrict__ fsr = swSym ? fsB : fsA;
    const float* __restrict__ fsi = swSym ? fsA : fsB;

    const float k = fwr[0];                     // 1/sqrt(33)

    // F_sym generator row: z[k] = F_sym[1][k]; F_sym[s][t] = z[(s*t)%5].
    float zr[SDIM], zi[SDIM];
    #pragma unroll
    for (int q = 0; q < SDIM; q++) { zr[q] = fsr[SDIM + q]; zi[q] = fsi[SDIM + q]; }

    // Compact F_sub load: rows w=1..16, cols v=0..16, interleaved.
    for (int i = tid; i < NPAIR * HALFW; i += THREADS) {
        const int w = i / HALFW + 1;
        const int c = i - (w - 1) * HALFW;
        sFcs[i] = make_float2(fwr[w * WDIM + c], fwi[w * WDIM + c]);
    }
    __syncthreads();

    const int ts = tid / HALFW;                 // tile slot 0..14
    const int v  = tid - ts * HALFW;            // 0..16
    int tile = blockIdx.x * TPB + ts;
    if (tile >= total_tiles) tile = 0;          // benign duplicate work on tail
    const int n = tile >> 4;                    // ADIM == 16
    const int a = tile & 15;
    const int vm = (v == 0) ? 0 : WDIM - v;     // mirror column

    // ---- Stage 1: T1[s] for columns v and vm; store Sigma/Delta (or T10) ----
    {
        float2 xa[SDIM], xb[SDIM];
        #pragma unroll
        for (int t = 0; t < SDIM; t++) {
            unsigned int base = (((unsigned int)n * SDIM + t) * ADIM + a) * WDIM;
            unsigned int iA = base + v;  if (iA >= xcount) iA = 0;
            unsigned int iB = base + vm; if (iB >= xcount) iB = 0;
            xa[t] = make_float2(xr[iA], xi[iA]);
            xb[t] = make_float2(xr[iB], xi[iB]);
        }
        #pragma unroll
        for (int s = 0; s < SDIM; s++) {
            float Ar = 0.f, Ai = 0.f, Br = 0.f, Bi = 0.f;
            #pragma unroll
            for (int t = 0; t < SDIM; t++) {
                const int I = (s * t) % SDIM;    // compile-time after unroll
                const float cr = zr[I], ci = zi[I];
                Ar += cr * xa[t].x - ci * xa[t].y;
                Ai += cr * xa[t].y + ci * xa[t].x;
                Br += cr * xb[t].x - ci * xb[t].y;
                Bi += cr * xb[t].y + ci * xb[t].x;
            }
            if (v == 0)
                sT10[ts][s] = make_float2(Ar, Ai);
            else
                sSD[ts][v - 1][s] = make_float4(Ar + Br, Ai + Bi, Ar - Br, Ai - Bi);
        }
    }
    __syncthreads();

    // ---- Stage 2: X[v], X[vm] via folded 33-pt DFT; then P, store (E,D) packed ----
    {
        float XrV[SDIM], XiV[SDIM], XrM[SDIM], XiM[SDIM];
        #pragma unroll
        for (int s = 0; s < SDIM; s++) {
            float2 t10 = sT10[ts][s];           // broadcast
            XrV[s] = k * t10.x;  XiV[s] = k * t10.y;
            XrM[s] = XrV[s];     XiM[s] = XiV[s];
        }
        #pragma unroll 4
        for (int w = 0; w < NPAIR; w++) {
            const float2 cs = sFcs[w * HALFW + v];
            const float c = cs.x, si = cs.y;
            #pragma unroll
            for (int s = 0; s < SDIM; s++) {
                const float4 sd = sSD[ts][w][s];     // broadcast
                XrV[s] += c * sd.x - si * sd.w;      // c*Sr - s*Di
                XiV[s] += c * sd.y + si * sd.z;      // c*Si + s*Dr
                XrM[s] += c * sd.x + si * sd.w;
                XiM[s] += c * sd.y - si * sd.z;
            }
        }
        float E[SDIM], D[SDIM];
        #pragma unroll
        for (int s = 0; s < SDIM; s++) {
            const float Pv = XrV[s] * XrV[s] + XiV[s] * XiV[s];
            const float Pm = XrM[s] * XrM[s] + XiM[s] * XiM[s];
            E[s] = Pv + Pm;  D[s] = Pv - Pm;
            if (v == 0) sP0[ts][s] = Pv;
        }
        if (v > 0) {
            sEDa[ts][v - 1] = make_float4(E[0], E[1], E[2], E[3]);
            sEDb[ts][v - 1] = make_float4(D[0], D[1], D[2], D[3]);
            sEDc[ts][v - 1] = make_float2(E[4], D[4]);
        }
    }
    __syncthreads();

    // ---- Stage 3: T2[s][v] = k*P0 + sum_w (E*c, -D*s), doubly folded ----
    float t2r[SDIM], t2i[SDIM];
    #pragma unroll
    for (int s = 0; s < SDIM; s++) {
        t2r[s] = k * sP0[ts][s];
        t2i[s] = 0.f;
    }
    #pragma unroll 4
    for (int w = 0; w < NPAIR; w++) {
        const float2 cs = sFcs[w * HALFW + v];
        const float4 Ea = sEDa[ts][w];               // broadcast
        const float4 Db = sEDb[ts][w];
        const float2 ec = sEDc[ts][w];
        t2r[0] += Ea.x * cs.x;  t2i[0] -= Db.x * cs.y;
        t2r[1] += Ea.y * cs.x;  t2i[1] -= Db.y * cs.y;
        t2r[2] += Ea.z * cs.x;  t2i[2] -= Db.z * cs.y;
        t2r[3] += Ea.w * cs.x;  t2i[3] -= Db.w * cs.y;
        t2r[4] += ec.x * cs.x;  t2i[4] -= ec.y * cs.y;
    }

    // ---- Stage 4: Y[sp][v] = sum_s conj(F_sym[s][sp]) * T2[s][v]; store + mirror ----
    #pragma unroll
    for (int sp = 0; sp < SDIM; sp++) {
        float yr = 0.f, yi = 0.f;
        #pragma unroll
        for (int s = 0; s < SDIM; s++) {
            const int I = (s * sp) % SDIM;           // compile-time after unroll
            const float cr = zr[I], ci = zi[I];
            yr += cr * t2r[s] + ci * t2i[s];
            yi += cr * t2i[s] - ci * t2r[s];
        }
        unsigned int oidx = (((unsigned int)n * SDIM + sp) * ADIM + a) * WDIM + v;
        if (real_only) {
            if (oidx < out_limit) outf[oidx] = yr;
        } else {
            if (2u * oidx + 1u < out_limit)
                reinterpret_cast<float2*>(outf)[oidx] = make_float2(yr, yi);
        }
        if (v > 0) {   // Hermitian mirror: Y[(5-sp)%5][33-v] = conj(Y[sp][v])
            const int sp2 = (SDIM - sp) % SDIM;
            unsigned int midx = (((unsigned int)n * SDIM + sp2) * ADIM + a) * WDIM + (WDIM - v);
            if (real_only) {
                if (midx < out_limit) outf[midx] = yr;
            } else {
                if (2u * midx + 1u < out_limit)
                    reinterpret_cast<float2*>(outf)[midx] = make_float2(yr, -yi);
            }
        }
    }
}

extern "C" void kernel_launch(void* const* d_in, const int* in_sizes, int n_in,
                              void* d_out, int out_size)
{
    long long big_raw = -1;
    for (int i = 0; i < n_in; i++)
        if ((long long)in_sizes[i] > big_raw) big_raw = in_sizes[i];

    const float *xr = 0, *xi = 0, *fsA = 0, *fsB = 0, *fwA = 0, *fwB = 0;
    int nsym = 0, nsub = 0, nbig = 0;
    for (int i = 0; i < n_in; i++) {
        const float* p = (const float*)d_in[i];
        long long c = in_sizes[i];
        if (c == SDIM * SDIM) {
            if (nsym++ == 0) fsA = p; else if (!fsB) fsB = p;
        } else if (c == WDIM * WDIM) {
            if (nsub++ == 0) fwA = p; else if (!fwB) fwB = p;
        } else if (c == big_raw) {
            if (nbig++ == 0) xr = p; else if (!xi) xi = p;
        }
    }
    if (!xr || !xi || !fsA || !fsB || !fwA || !fwB) return;

    const long long C = big_raw;
    const int N = (int)(C / (SDIM * ADIM * WDIM));
    const int total_tiles = N * ADIM;
    if (total_tiles <= 0) return;
    const int blocks = (total_tiles + TPB - 1) / TPB;

    const int real_only = ((long long)out_size >= 2 * C) ? 0 : 1;

    autocorr_kernel<<<blocks, THREADS>>>(
        xr, xi, fsA, fsB, fwA, fwB, (float*)d_out, total_tiles,
        (unsigned int)C, (unsigned int)out_size, real_only);
}

// round 9
// speedup vs baseline: 2.0055x; 1.1460x over previous
#include <cuda_runtime.h>

// SymbolSubcarrierAutocorrelation — Round 9: register blocking vs smem delivery BW.
//   * 8 pair-threads/tile, each owning 2 conjugate column-pairs (4 columns):
//     every broadcast (S,D)/(E,D) float4 now feeds 4 outputs -> smem wavefronts ~0.53x
//   * v=0 handled by dedicated warp-coherent threads (F_sub[w][0]=k real):
//     X0 = k*(T10 + sum S), t2(0) = k*(P0 + sum E)
//   * F_sub repacked as (c0,s0,c1,s1) float4 per (w, thread) -> 1 LDS.128/w/stage

#define SDIM 5
#define WDIM 33
#define ADIM 16
#define NPAIR 16
#define TPB 28
#define PAIRT (TPB * 8)        // 224 pair-threads
#define THREADS (PAIRT + TPB)  // 252 (+28 v0-threads)

__global__ __launch_bounds__(THREADS)
void autocorr_kernel(const float* __restrict__ xr, const float* __restrict__ xi,
                     const float* __restrict__ fsA, const float* __restrict__ fsB,
                     const float* __restrict__ fwA, const float* __restrict__ fwB,
                     float* __restrict__ outf,
                     int total_tiles,
                     unsigned int xcount,
                     unsigned int out_limit,
                     int real_only)
{
    __shared__ float4 sF4[NPAIR * 8];           // (w, j): F[w+1][2j+1].re,.im, F[w+1][2j+2].re,.im
    __shared__ float4 sSD [TPB][NPAIR][SDIM];   // (Sr, Si, Dr, Di)
    __shared__ float2 sT10[TPB][SDIM];
    __shared__ float4 sEDa[TPB][NPAIR];         // E0..E3
    __shared__ float4 sEDb[TPB][NPAIR];         // D0..D3
    __shared__ float2 sEDc[TPB][NPAIR];         // (E4, D4)
    __shared__ float  sP0 [TPB][SDIM];

    const int tid = threadIdx.x;

    const bool swSub = (fabsf(fwA[0]) < 1e-3f);
    const bool swSym = (fabsf(fsA[0]) < 1e-3f);
    const float* __restrict__ fwr = swSub ? fwB : fwA;
    const float* __restrict__ fwi = swSub ? fwA : fwB;
    const float* __restrict__ fsr = swSym ? fsB : fsA;
    const float* __restrict__ fsi = swSym ? fsA : fsB;

    const float k = fwr[0];                     // 1/sqrt(33)

    float zr[SDIM], zi[SDIM];                   // F_sym[s][t] = z[(s*t)%5]
    #pragma unroll
    for (int q = 0; q < SDIM; q++) { zr[q] = fsr[SDIM + q]; zi[q] = fsi[SDIM + q]; }

    if (tid < NPAIR * 8) {
        const int w = tid >> 3, j = tid & 7;
        const int c1 = 2 * j + 1, c2 = 2 * j + 2;
        sF4[tid] = make_float4(fwr[(w + 1) * WDIM + c1], fwi[(w + 1) * WDIM + c1],
                               fwr[(w + 1) * WDIM + c2], fwi[(w + 1) * WDIM + c2]);
    }
    __syncthreads();

    const bool isV0 = (tid >= PAIRT);
    int ts, j;
    if (isV0) { ts = tid - PAIRT; j = 0; }
    else      { ts = tid >> 3;    j = tid & 7; }
    int tile = blockIdx.x * TPB + ts;
    if (tile >= total_tiles) tile = 0;
    const int n = tile >> 4;                    // ADIM == 16
    const int a = tile & 15;
    const unsigned int rowbase0 = (((unsigned int)n * SDIM) * ADIM + a) * WDIM;

    // ---- Stage 1 ----
    if (!isV0) {
        #pragma unroll
        for (int pc = 0; pc < 2; pc++) {
            const int v = 2 * j + 1 + pc;
            const int vm = WDIM - v;
            float2 xa[SDIM], xb[SDIM];
            #pragma unroll
            for (int t = 0; t < SDIM; t++) {
                unsigned int base = rowbase0 + (unsigned int)t * (ADIM * WDIM);
                unsigned int iA = base + v;  if (iA >= xcount) iA = 0;
                unsigned int iB = base + vm; if (iB >= xcount) iB = 0;
                xa[t] = make_float2(xr[iA], xi[iA]);
                xb[t] = make_float2(xr[iB], xi[iB]);
            }
            #pragma unroll
            for (int s = 0; s < SDIM; s++) {
                float Ar = 0.f, Ai = 0.f, Br = 0.f, Bi = 0.f;
                #pragma unroll
                for (int t = 0; t < SDIM; t++) {
                    const int I = (s * t) % SDIM;
                    const float cr = zr[I], ci = zi[I];
                    Ar += cr * xa[t].x - ci * xa[t].y;
                    Ai += cr * xa[t].y + ci * xa[t].x;
                    Br += cr * xb[t].x - ci * xb[t].y;
                    Bi += cr * xb[t].y + ci * xb[t].x;
                }
                sSD[ts][v - 1][s] = make_float4(Ar + Br, Ai + Bi, Ar - Br, Ai - Bi);
            }
        }
    } else {
        float2 x0[SDIM];
        #pragma unroll
        for (int t = 0; t < SDIM; t++) {
            unsigned int iA = rowbase0 + (unsigned int)t * (ADIM * WDIM);
            if (iA >= xcount) iA = 0;
            x0[t] = make_float2(xr[iA], xi[iA]);
        }
        #pragma unroll
        for (int s = 0; s < SDIM; s++) {
            float Ar = 0.f, Ai = 0.f;
            #pragma unroll
            for (int t = 0; t < SDIM; t++) {
                const int I = (s * t) % SDIM;
                Ar += zr[I] * x0[t].x - zi[I] * x0[t].y;
                Ai += zr[I] * x0[t].y + zi[I] * x0[t].x;
            }
            sT10[ts][s] = make_float2(Ar, Ai);
        }
    }
    __syncthreads();

    // ---- Stage 2 ----
    if (!isV0) {
        // Columns: [0]=p0 fwd, [1]=p0 mirror, [2]=p1 fwd, [3]=p1 mirror
        float Xr[4][SDIM], Xi[4][SDIM];
        #pragma unroll
        for (int s = 0; s < SDIM; s++) {
            const float2 t10 = sT10[ts][s];
            const float br = k * t10.x, bi = k * t10.y;
            #pragma unroll
            for (int c = 0; c < 4; c++) { Xr[c][s] = br; Xi[c][s] = bi; }
        }
        #pragma unroll 4
        for (int w = 0; w < NPAIR; w++) {
            const float4 f = sF4[w * 8 + j];    // c0,s0,c1,s1
            #pragma unroll
            for (int s = 0; s < SDIM; s++) {
                const float4 sd = sSD[ts][w][s];
                {
                    const float pa = f.x * sd.x, pb = f.y * sd.w;
                    const float pc_ = f.x * sd.y, pd = f.y * sd.z;
                    Xr[0][s] += pa - pb;  Xi[0][s] += pc_ + pd;
                    Xr[1][s] += pa + pb;  Xi[1][s] += pc_ - pd;
                }
                {
                    const float pa = f.z * sd.x, pb = f.w * sd.w;
                    const float pc_ = f.z * sd.y, pd = f.w * sd.z;
                    Xr[2][s] += pa - pb;  Xi[2][s] += pc_ + pd;
                    Xr[3][s] += pa + pb;  Xi[3][s] += pc_ - pd;
                }
            }
        }
        #pragma unroll
        for (int pc = 0; pc < 2; pc++) {
            float E[SDIM], D[SDIM];
            #pragma unroll
            for (int s = 0; s < SDIM; s++) {
                const float Pv = Xr[2*pc][s] * Xr[2*pc][s] + Xi[2*pc][s] * Xi[2*pc][s];
                const float Pm = Xr[2*pc+1][s] * Xr[2*pc+1][s] + Xi[2*pc+1][s] * Xi[2*pc+1][s];
                E[s] = Pv + Pm;  D[s] = Pv - Pm;
            }
            const int idx = 2 * j + pc;
            sEDa[ts][idx] = make_float4(E[0], E[1], E[2], E[3]);
            sEDb[ts][idx] = make_float4(D[0], D[1], D[2], D[3]);
            sEDc[ts][idx] = make_float2(E[4], D[4]);
        }
    } else {
        float sr[SDIM] = {0,0,0,0,0}, sm[SDIM] = {0,0,0,0,0};
        #pragma unroll 4
        for (int w = 0; w < NPAIR; w++) {
            #pragma unroll
            for (int s = 0; s < SDIM; s++) {
                const float2 sv = *reinterpret_cast<const float2*>(&sSD[ts][w][s]);
                sr[s] += sv.x;  sm[s] += sv.y;
            }
        }
        #pragma unroll
        for (int s = 0; s < SDIM; s++) {
            const float X0r = k * (sT10[ts][s].x + sr[s]);
            const float X0i = k * (sT10[ts][s].y + sm[s]);
            sP0[ts][s] = X0r * X0r + X0i * X0i;
        }
    }
    __syncthreads();

    // ---- Stage 3 + 4 ----
    if (!isV0) {
        float t2r[2][SDIM], t2i[2][SDIM];
        #pragma unroll
        for (int s = 0; s < SDIM; s++) {
            const float b = k * sP0[ts][s];
            t2r[0][s] = b; t2r[1][s] = b;
            t2i[0][s] = 0.f; t2i[1][s] = 0.f;
        }
        #pragma unroll 4
        for (int w = 0; w < NPAIR; w++) {
            const float4 f  = sF4[w * 8 + j];
            const float4 Ea = sEDa[ts][w];
            const float4 Db = sEDb[ts][w];
            const float2 ec = sEDc[ts][w];
            t2r[0][0] += Ea.x * f.x;  t2i[0][0] -= Db.x * f.y;
            t2r[0][1] += Ea.y * f.x;  t2i[0][1] -= Db.y * f.y;
            t2r[0][2] += Ea.z * f.x;  t2i[0][2] -= Db.z * f.y;
            t2r[0][3] += Ea.w * f.x;  t2i[0][3] -= Db.w * f.y;
            t2r[0][4] += ec.x * f.x;  t2i[0][4] -= ec.y * f.y;
            t2r[1][0] += Ea.x * f.z;  t2i[1][0] -= Db.x * f.w;
            t2r[1][1] += Ea.y * f.z;  t2i[1][1] -= Db.y * f.w;
            t2r[1][2] += Ea.z * f.z;  t2i[1][2] -= Db.z * f.w;
            t2r[1][3] += Ea.w * f.z;  t2i[1][3] -= Db.w * f.w;
            t2r[1][4] += ec.x * f.z;  t2i[1][4] -= ec.y * f.w;
        }
        #pragma unroll
        for (int pc = 0; pc < 2; pc++) {
            const int v = 2 * j + 1 + pc;
            #pragma unroll
            for (int sp = 0; sp < SDIM; sp++) {
                float yr = 0.f, yi = 0.f;
                #pragma unroll
                for (int s = 0; s < SDIM; s++) {
                    const int I = (s * sp) % SDIM;
                    yr += zr[I] * t2r[pc][s] + zi[I] * t2i[pc][s];
                    yi += zr[I] * t2i[pc][s] - zi[I] * t2r[pc][s];
                }
                unsigned int oidx = (((unsigned int)n * SDIM + sp) * ADIM + a) * WDIM + v;
                const int sp2 = (SDIM - sp) % SDIM;
                unsigned int midx = (((unsigned int)n * SDIM + sp2) * ADIM + a) * WDIM + (WDIM - v);
                if (real_only) {
                    if (oidx < out_limit) outf[oidx] = yr;
                    if (midx < out_limit) outf[midx] = yr;
                } else {
                    if (2u * oidx + 1u < out_limit)
                        reinterpret_cast<float2*>(outf)[oidx] = make_float2(yr, yi);
                    if (2u * midx + 1u < out_limit)
                        reinterpret_cast<float2*>(outf)[midx] = make_float2(yr, -yi);
                }
            }
        }
    } else {
        float accE[SDIM] = {0,0,0,0,0};
        #pragma unroll 4
        for (int w = 0; w < NPAIR; w++) {
            const float4 Ea = sEDa[ts][w];
            const float2 ec = sEDc[ts][w];
            accE[0] += Ea.x; accE[1] += Ea.y; accE[2] += Ea.z; accE[3] += Ea.w;
            accE[4] += ec.x;
        }
        float t2r0[SDIM];
        #pragma unroll
        for (int s = 0; s < SDIM; s++)
            t2r0[s] = k * (sP0[ts][s] + accE[s]);
        #pragma unroll
        for (int sp = 0; sp < SDIM; sp++) {
            float yr = 0.f, yi = 0.f;
            #pragma unroll
            for (int s = 0; s < SDIM; s++) {
                const int I = (s * sp) % SDIM;
                yr += zr[I] * t2r0[s];
                yi -= zi[I] * t2r0[s];
            }
            unsigned int oidx = (((unsigned int)n * SDIM + sp) * ADIM + a) * WDIM;
            if (real_only) {
                if (oidx < out_limit) outf[oidx] = yr;
            } else {
                if (2u * oidx + 1u < out_limit)
                    reinterpret_cast<float2*>(outf)[oidx] = make_float2(yr, yi);
            }
        }
    }
}

extern "C" void kernel_launch(void* const* d_in, const int* in_sizes, int n_in,
                              void* d_out, int out_size)
{
    long long big_raw = -1;
    for (int i = 0; i < n_in; i++)
        if ((long long)in_sizes[i] > big_raw) big_raw = in_sizes[i];

    const float *xr = 0, *xi = 0, *fsA = 0, *fsB = 0, *fwA = 0, *fwB = 0;
    int nsym = 0, nsub = 0, nbig = 0;
    for (int i = 0; i < n_in; i++) {
        const float* p = (const float*)d_in[i];
        long long c = in_sizes[i];
        if (c == SDIM * SDIM) {
            if (nsym++ == 0) fsA = p; else if (!fsB) fsB = p;
        } else if (c == WDIM * WDIM) {
            if (nsub++ == 0) fwA = p; else if (!fwB) fwB = p;
        } else if (c == big_raw) {
            if (nbig++ == 0) xr = p; else if (!xi) xi = p;
        }
    }
    if (!xr || !xi || !fsA || !fsB || !fwA || !fwB) return;

    const long long C = big_raw;
    const int N = (int)(C / (SDIM * ADIM * WDIM));
    const int total_tiles = N * ADIM;
    if (total_tiles <= 0) return;
    const int blocks = (total_tiles + TPB - 1) / TPB;

    const int real_only = ((long long)out_size >= 2 * C) ? 0 : 1;

    autocorr_kernel<<<blocks, THREADS>>>(
        xr, xi, fsA, fsB, fwA, fwB, (float*)d_out, total_tiles,
        (unsigned int)C, (unsigned int)out_size, real_only);
}

// round 10
// speedup vs baseline: 2.0834x; 1.0389x over previous
#include <cuda_runtime.h>

// SymbolSubcarrierAutocorrelation — Round 10: occupancy (register) fix.
//   * Stage-2 split over s ({0,1,2} then {3,4}): live accums 40 -> 24, no extra sd traffic
//   * __launch_bounds__(252, 4): <=64 regs -> 4 blocks/SM (was reg-capped at 3)
//   * sED unioned into sSD region (E/D carried in regs across one extra barrier):
//     smem 57KB -> 39.7KB
// Algebra identical to Round 9 (conjugate-pair folded, Hermitian mirrors, v0 threads).

#define SDIM 5
#define WDIM 33
#define ADIM 16
#define NPAIR 16
#define TPB 28
#define PAIRT (TPB * 8)        // 224 pair-threads
#define THREADS (PAIRT + TPB)  // 252 (+28 v0-threads)

#define SSD_BYTES (TPB * NPAIR * SDIM * 16)        // 35840
#define EDA_OFF   0                                // float4 [TPB][NPAIR] = 7168
#define EDB_OFF   (TPB * NPAIR * 16)               // 7168
#define EDC_OFF   (2 * TPB * NPAIR * 16)           // 14336 (+3584 = 17920 <= 35840)

__global__ __launch_bounds__(THREADS, 4)
void autocorr_kernel(const float* __restrict__ xr, const float* __restrict__ xi,
                     const float* __restrict__ fsA, const float* __restrict__ fsB,
                     const float* __restrict__ fwA, const float* __restrict__ fwB,
                     float* __restrict__ outf,
                     int total_tiles,
                     unsigned int xcount,
                     unsigned int out_limit,
                     int real_only)
{
    __shared__ __align__(16) char uS[SSD_BYTES];   // phase A/B: sSD; phase C/D: sED
    __shared__ float4 sF4[NPAIR * 8];
    __shared__ float2 sT10[TPB][SDIM];
    __shared__ float  sP0 [TPB][SDIM];

    float4* const sSD  = reinterpret_cast<float4*>(uS);            // [TPB][NPAIR][SDIM]
    float4* const sEDa = reinterpret_cast<float4*>(uS + EDA_OFF);  // [TPB][NPAIR] E0..3
    float4* const sEDb = reinterpret_cast<float4*>(uS + EDB_OFF);  // [TPB][NPAIR] D0..3
    float2* const sEDc = reinterpret_cast<float2*>(uS + EDC_OFF);  // [TPB][NPAIR] (E4,D4)

    const int tid = threadIdx.x;

    const bool swSub = (fabsf(fwA[0]) < 1e-3f);
    const bool swSym = (fabsf(fsA[0]) < 1e-3f);
    const float* __restrict__ fwr = swSub ? fwB : fwA;
    const float* __restrict__ fwi = swSub ? fwA : fwB;
    const float* __restrict__ fsr = swSym ? fsB : fsA;
    const float* __restrict__ fsi = swSym ? fsA : fsB;

    const float k = fwr[0];                     // 1/sqrt(33)

    float zr[SDIM], zi[SDIM];                   // F_sym[s][t] = z[(s*t)%5]
    #pragma unroll
    for (int q = 0; q < SDIM; q++) { zr[q] = fsr[SDIM + q]; zi[q] = fsi[SDIM + q]; }

    if (tid < NPAIR * 8) {
        const int w = tid >> 3, j = tid & 7;
        const int c1 = 2 * j + 1, c2 = 2 * j + 2;
        sF4[tid] = make_float4(fwr[(w + 1) * WDIM + c1], fwi[(w + 1) * WDIM + c1],
                               fwr[(w + 1) * WDIM + c2], fwi[(w + 1) * WDIM + c2]);
    }

    const bool isV0 = (tid >= PAIRT);
    int ts, j;
    if (isV0) { ts = tid - PAIRT; j = 0; }
    else      { ts = tid >> 3;    j = tid & 7; }
    int tile = blockIdx.x * TPB + ts;
    if (tile >= total_tiles) tile = 0;
    const int n = tile >> 4;                    // ADIM == 16
    const int a = tile & 15;
    const unsigned int rowbase0 = (((unsigned int)n * SDIM) * ADIM + a) * WDIM;
    __syncthreads();                            // sF4 ready (also covers uS reuse)

    // ---- Phase A: stage 1 ----
    if (!isV0) {
        #pragma unroll
        for (int pc = 0; pc < 2; pc++) {
            const int v = 2 * j + 1 + pc;
            const int vm = WDIM - v;
            float2 xa[SDIM], xb[SDIM];
            #pragma unroll
            for (int t = 0; t < SDIM; t++) {
                unsigned int base = rowbase0 + (unsigned int)t * (ADIM * WDIM);
                unsigned int iA = base + v;  if (iA >= xcount) iA = 0;
                unsigned int iB = base + vm; if (iB >= xcount) iB = 0;
                xa[t] = make_float2(xr[iA], xi[iA]);
                xb[t] = make_float2(xr[iB], xi[iB]);
            }
            #pragma unroll
            for (int s = 0; s < SDIM; s++) {
                float Ar = 0.f, Ai = 0.f, Br = 0.f, Bi = 0.f;
                #pragma unroll
                for (int t = 0; t < SDIM; t++) {
                    const int I = (s * t) % SDIM;
                    const float cr = zr[I], ci = zi[I];
                    Ar += cr * xa[t].x - ci * xa[t].y;
                    Ai += cr * xa[t].y + ci * xa[t].x;
                    Br += cr * xb[t].x - ci * xb[t].y;
                    Bi += cr * xb[t].y + ci * xb[t].x;
                }
                sSD[(ts * NPAIR + (v - 1)) * SDIM + s] =
                    make_float4(Ar + Br, Ai + Bi, Ar - Br, Ai - Bi);
            }
        }
    } else {
        float2 x0[SDIM];
        #pragma unroll
        for (int t = 0; t < SDIM; t++) {
            unsigned int iA = rowbase0 + (unsigned int)t * (ADIM * WDIM);
            if (iA >= xcount) iA = 0;
            x0[t] = make_float2(xr[iA], xi[iA]);
        }
        #pragma unroll
        for (int s = 0; s < SDIM; s++) {
            float Ar = 0.f, Ai = 0.f;
            #pragma unroll
            for (int t = 0; t < SDIM; t++) {
                const int I = (s * t) % SDIM;
                Ar += zr[I] * x0[t].x - zi[I] * x0[t].y;
                Ai += zr[I] * x0[t].y + zi[I] * x0[t].x;
            }
            sT10[ts][s] = make_float2(Ar, Ai);
        }
    }
    __syncthreads();

    // ---- Phase B: stage 2 (s-split, E/D kept in registers) ----
    float Ereg[SDIM], Dreg[2][SDIM];            // pair-threads: E/D for both owned pairs
    float Ereg2[SDIM];
    if (!isV0) {
        #pragma unroll
        for (int g = 0; g < 2; g++) {
            const int s0 = g ? 3 : 0;
            const int ns = g ? 2 : 3;
            float Xr[4][3], Xi[4][3];
            #pragma unroll
            for (int ss = 0; ss < 3; ss++) {
                if (ss < ns) {
                    const float2 t10 = sT10[ts][s0 + ss];
                    const float br = k * t10.x, bi = k * t10.y;
                    #pragma unroll
                    for (int c = 0; c < 4; c++) { Xr[c][ss] = br; Xi[c][ss] = bi; }
                }
            }
            #pragma unroll 4
            for (int w = 0; w < NPAIR; w++) {
                const float4 f = sF4[w * 8 + j];
                #pragma unroll
                for (int ss = 0; ss < 3; ss++) {
                    if (ss < ns) {
                        const float4 sd = sSD[(ts * NPAIR + w) * SDIM + s0 + ss];
                        {
                            const float pa = f.x * sd.x, pb = f.y * sd.w;
                            const float pc_ = f.x * sd.y, pd = f.y * sd.z;
                            Xr[0][ss] += pa - pb;  Xi[0][ss] += pc_ + pd;
                            Xr[1][ss] += pa + pb;  Xi[1][ss] += pc_ - pd;
                        }
                        {
                            const float pa = f.z * sd.x, pb = f.w * sd.w;
                            const float pc_ = f.z * sd.y, pd = f.w * sd.z;
                            Xr[2][ss] += pa - pb;  Xi[2][ss] += pc_ + pd;
                            Xr[3][ss] += pa + pb;  Xi[3][ss] += pc_ - pd;
                        }
                    }
                }
            }
            #pragma unroll
            for (int ss = 0; ss < 3; ss++) {
                if (ss < ns) {
                    const int s = s0 + ss;
                    const float Pv0 = Xr[0][ss]*Xr[0][ss] + Xi[0][ss]*Xi[0][ss];
                    const float Pm0 = Xr[1][ss]*Xr[1][ss] + Xi[1][ss]*Xi[1][ss];
                    const float Pv1 = Xr[2][ss]*Xr[2][ss] + Xi[2][ss]*Xi[2][ss];
                    const float Pm1 = Xr[3][ss]*Xr[3][ss] + Xi[3][ss]*Xi[3][ss];
                    Ereg[s]    = Pv0 + Pm0;  Dreg[0][s] = Pv0 - Pm0;
                    Ereg2[s]   = Pv1 + Pm1;  Dreg[1][s] = Pv1 - Pm1;
                }
            }
        }
    } else {
        float sr[SDIM] = {0,0,0,0,0}, sm[SDIM] = {0,0,0,0,0};
        #pragma unroll 4
        for (int w = 0; w < NPAIR; w++) {
            #pragma unroll
            for (int s = 0; s < SDIM; s++) {
                const float2 sv = *reinterpret_cast<const float2*>(
                    &sSD[(ts * NPAIR + w) * SDIM + s]);
                sr[s] += sv.x;  sm[s] += sv.y;
            }
        }
        #pragma unroll
        for (int s = 0; s < SDIM; s++) {
            const float X0r = k * (sT10[ts][s].x + sr[s]);
            const float X0i = k * (sT10[ts][s].y + sm[s]);
            sP0[ts][s] = X0r * X0r + X0i * X0i;
        }
    }
    __syncthreads();                             // all sSD reads complete

    // ---- Phase C: publish E/D into union region ----
    if (!isV0) {
        const int i0 = ts * NPAIR + 2 * j;
        sEDa[i0]     = make_float4(Ereg[0],  Ereg[1],  Ereg[2],  Ereg[3]);
        sEDb[i0]     = make_float4(Dreg[0][0], Dreg[0][1], Dreg[0][2], Dreg[0][3]);
        sEDc[i0]     = make_float2(Ereg[4],  Dreg[0][4]);
        sEDa[i0 + 1] = make_float4(Ereg2[0], Ereg2[1], Ereg2[2], Ereg2[3]);
        sEDb[i0 + 1] = make_float4(Dreg[1][0], Dreg[1][1], Dreg[1][2], Dreg[1][3]);
        sEDc[i0 + 1] = make_float2(Ereg2[4], Dreg[1][4]);
    }
    __syncthreads();

    // ---- Phase D: stages 3 + 4 ----
    if (!isV0) {
        float t2r[2][SDIM], t2i[2][SDIM];
        #pragma unroll
        for (int s = 0; s < SDIM; s++) {
            const float b = k * sP0[ts][s];
            t2r[0][s] = b; t2r[1][s] = b;
            t2i[0][s] = 0.f; t2i[1][s] = 0.f;
        }
        #pragma unroll 4
        for (int w = 0; w < NPAIR; w++) {
            const float4 f  = sF4[w * 8 + j];
            const float4 Ea = sEDa[ts * NPAIR + w];
            const float4 Db = sEDb[ts * NPAIR + w];
            const float2 ec = sEDc[ts * NPAIR + w];
            t2r[0][0] += Ea.x * f.x;  t2i[0][0] -= Db.x * f.y;
            t2r[0][1] += Ea.y * f.x;  t2i[0][1] -= Db.y * f.y;
            t2r[0][2] += Ea.z * f.x;  t2i[0][2] -= Db.z * f.y;
            t2r[0][3] += Ea.w * f.x;  t2i[0][3] -= Db.w * f.y;
            t2r[0][4] += ec.x * f.x;  t2i[0][4] -= ec.y * f.y;
            t2r[1][0] += Ea.x * f.z;  t2i[1][0] -= Db.x * f.w;
            t2r[1][1] += Ea.y * f.z;  t2i[1][1] -= Db.y * f.w;
            t2r[1][2] += Ea.z * f.z;  t2i[1][2] -= Db.z * f.w;
            t2r[1][3] += Ea.w * f.z;  t2i[1][3] -= Db.w * f.w;
            t2r[1][4] += ec.x * f.z;  t2i[1][4] -= ec.y * f.w;
        }
        #pragma unroll
        for (int pc = 0; pc < 2; pc++) {
            const int v = 2 * j + 1 + pc;
            #pragma unroll
            for (int sp = 0; sp < SDIM; sp++) {
                float yr = 0.f, yi = 0.f;
                #pragma unroll
                for (int s = 0; s < SDIM; s++) {
                    const int I = (s * sp) % SDIM;
                    yr += zr[I] * t2r[pc][s] + zi[I] * t2i[pc][s];
                    yi += zr[I] * t2i[pc][s] - zi[I] * t2r[pc][s];
                }
                unsigned int oidx = (((unsigned int)n * SDIM + sp) * ADIM + a) * WDIM + v;
                const int sp2 = (SDIM - sp) % SDIM;
                unsigned int midx = (((unsigned int)n * SDIM + sp2) * ADIM + a) * WDIM + (WDIM - v);
                if (real_only) {
                    if (oidx < out_limit) outf[oidx] = yr;
                    if (midx < out_limit) outf[midx] = yr;
                } else {
                    if (2u * oidx + 1u < out_limit)
                        reinterpret_cast<float2*>(outf)[oidx] = make_float2(yr, yi);
                    if (2u * midx + 1u < out_limit)
                        reinterpret_cast<float2*>(outf)[midx] = make_float2(yr, -yi);
                }
            }
        }
    } else {
        float accE[SDIM] = {0,0,0,0,0};
        #pragma unroll 4
        for (int w = 0; w < NPAIR; w++) {
            const float4 Ea = sEDa[ts * NPAIR + w];
            const float2 ec = sEDc[ts * NPAIR + w];
            accE[0] += Ea.x; accE[1] += Ea.y; accE[2] += Ea.z; accE[3] += Ea.w;
            accE[4] += ec.x;
        }
        float t2r0[SDIM];
        #pragma unroll
        for (int s = 0; s < SDIM; s++)
            t2r0[s] = k * (sP0[ts][s] + accE[s]);
        #pragma unroll
        for (int sp = 0; sp < SDIM; sp++) {
            float yr = 0.f, yi = 0.f;
            #pragma unroll
            for (int s = 0; s < SDIM; s++) {
                const int I = (s * sp) % SDIM;
                yr += zr[I] * t2r0[s];
                yi -= zi[I] * t2r0[s];
            }
            unsigned int oidx = (((unsigned int)n * SDIM + sp) * ADIM + a) * WDIM;
            if (real_only) {
                if (oidx < out_limit) outf[oidx] = yr;
            } else {
                if (2u * oidx + 1u < out_limit)
                    reinterpret_cast<float2*>(outf)[oidx] = make_float2(yr, yi);
            }
        }
    }
}

extern "C" void kernel_launch(void* const* d_in, const int* in_sizes, int n_in,
                              void* d_out, int out_size)
{
    long long big_raw = -1;
    for (int i = 0; i < n_in; i++)
        if ((long long)in_sizes[i] > big_raw) big_raw = in_sizes[i];

    const float *xr = 0, *xi = 0, *fsA = 0, *fsB = 0, *fwA = 0, *fwB = 0;
    int nsym = 0, nsub = 0, nbig = 0;
    for (int i = 0; i < n_in; i++) {
        const float* p = (const float*)d_in[i];
        long long c = in_sizes[i];
        if (c == SDIM * SDIM) {
            if (nsym++ == 0) fsA = p; else if (!fsB) fsB = p;
        } else if (c == WDIM * WDIM) {
            if (nsub++ == 0) fwA = p; else if (!fwB) fwB = p;
        } else if (c == big_raw) {
            if (nbig++ == 0) xr = p; else if (!xi) xi = p;
        }
    }
    if (!xr || !xi || !fsA || !fsB || !fwA || !fwB) return;

    const long long C = big_raw;
    const int N = (int)(C / (SDIM * ADIM * WDIM));
    const int total_tiles = N * ADIM;
    if (total_tiles <= 0) return;
    const int blocks = (total_tiles + TPB - 1) / TPB;

    const int real_only = ((long long)out_size >= 2 * C) ? 0 : 1;

    autocorr_kernel<<<blocks, THREADS>>>(
        xr, xi, fsA, fsB, fwA, fwB, (float*)d_out, total_tiles,
        (unsigned int)C, (unsigned int)out_size, real_only);
}

// round 11
// speedup vs baseline: 2.1784x; 1.0456x over previous
#include <cuda_runtime.h>

// SymbolSubcarrierAutocorrelation — Round 11: twiddles by rotation recurrence.
//   F_sub[w][v] = F_sub[1][v] * r^(w-1), r = sqrt(33)*F_sub[1][v]  (unit rotation)
//   -> sF4 smem array deleted; 48 LDS.128/thread replaced by ~8 FFMA/w-step.
//   Trades L1 (81% busy, the limiter) for FMA (40% busy). Rest identical to R10.

#define SDIM 5
#define WDIM 33
#define ADIM 16
#define NPAIR 16
#define TPB 28
#define PAIRT (TPB * 8)        // 224 pair-threads
#define THREADS (PAIRT + TPB)  // 252 (+28 v0-threads)

#define SSD_BYTES (TPB * NPAIR * SDIM * 16)        // 35840
#define EDA_OFF   0
#define EDB_OFF   (TPB * NPAIR * 16)               // 7168
#define EDC_OFF   (2 * TPB * NPAIR * 16)           // 14336

__global__ __launch_bounds__(THREADS, 4)
void autocorr_kernel(const float* __restrict__ xr, const float* __restrict__ xi,
                     const float* __restrict__ fsA, const float* __restrict__ fsB,
                     const float* __restrict__ fwA, const float* __restrict__ fwB,
                     float* __restrict__ outf,
                     int total_tiles,
                     unsigned int xcount,
                     unsigned int out_limit,
                     int real_only)
{
    __shared__ __align__(16) char uS[SSD_BYTES];   // phase A/B: sSD; phase C/D: sED
    __shared__ float2 sT10[TPB][SDIM];
    __shared__ float  sP0 [TPB][SDIM];

    float4* const sSD  = reinterpret_cast<float4*>(uS);
    float4* const sEDa = reinterpret_cast<float4*>(uS + EDA_OFF);
    float4* const sEDb = reinterpret_cast<float4*>(uS + EDB_OFF);
    float2* const sEDc = reinterpret_cast<float2*>(uS + EDC_OFF);

    const int tid = threadIdx.x;

    const bool swSub = (fabsf(fwA[0]) < 1e-3f);
    const bool swSym = (fabsf(fsA[0]) < 1e-3f);
    const float* __restrict__ fwr = swSub ? fwB : fwA;
    const float* __restrict__ fwi = swSub ? fwA : fwB;
    const float* __restrict__ fsr = swSym ? fsB : fsA;
    const float* __restrict__ fsi = swSym ? fsA : fsB;

    const float k = fwr[0];                     // 1/sqrt(33)
    const float invk = 1.0f / k;                // sqrt(33)

    float zr[SDIM], zi[SDIM];                   // F_sym[s][t] = z[(s*t)%5]
    #pragma unroll
    for (int q = 0; q < SDIM; q++) { zr[q] = fsr[SDIM + q]; zi[q] = fsi[SDIM + q]; }

    const bool isV0 = (tid >= PAIRT);
    int ts, j;
    if (isV0) { ts = tid - PAIRT; j = 0; }
    else      { ts = tid >> 3;    j = tid & 7; }
    int tile = blockIdx.x * TPB + ts;
    if (tile >= total_tiles) tile = 0;
    const int n = tile >> 4;                    // ADIM == 16
    const int a = tile & 15;
    const unsigned int rowbase0 = (((unsigned int)n * SDIM) * ADIM + a) * WDIM;
    const int c1 = 2 * j + 1, c2 = 2 * j + 2;   // owned columns (pair threads)

    // ---- Phase A: stage 1 ----
    if (!isV0) {
        #pragma unroll
        for (int pc = 0; pc < 2; pc++) {
            const int v = 2 * j + 1 + pc;
            const int vm = WDIM - v;
            float2 xa[SDIM], xb[SDIM];
            #pragma unroll
            for (int t = 0; t < SDIM; t++) {
                unsigned int base = rowbase0 + (unsigned int)t * (ADIM * WDIM);
                unsigned int iA = base + v;  if (iA >= xcount) iA = 0;
                unsigned int iB = base + vm; if (iB >= xcount) iB = 0;
                xa[t] = make_float2(xr[iA], xi[iA]);
                xb[t] = make_float2(xr[iB], xi[iB]);
            }
            #pragma unroll
            for (int s = 0; s < SDIM; s++) {
                float Ar = 0.f, Ai = 0.f, Br = 0.f, Bi = 0.f;
                #pragma unroll
                for (int t = 0; t < SDIM; t++) {
                    const int I = (s * t) % SDIM;
                    const float cr = zr[I], ci = zi[I];
                    Ar += cr * xa[t].x - ci * xa[t].y;
                    Ai += cr * xa[t].y + ci * xa[t].x;
                    Br += cr * xb[t].x - ci * xb[t].y;
                    Bi += cr * xb[t].y + ci * xb[t].x;
                }
                sSD[(ts * NPAIR + (v - 1)) * SDIM + s] =
                    make_float4(Ar + Br, Ai + Bi, Ar - Br, Ai - Bi);
            }
        }
    } else {
        float2 x0[SDIM];
        #pragma unroll
        for (int t = 0; t < SDIM; t++) {
            unsigned int iA = rowbase0 + (unsigned int)t * (ADIM * WDIM);
            if (iA >= xcount) iA = 0;
            x0[t] = make_float2(xr[iA], xi[iA]);
        }
        #pragma unroll
        for (int s = 0; s < SDIM; s++) {
            float Ar = 0.f, Ai = 0.f;
            #pragma unroll
            for (int t = 0; t < SDIM; t++) {
                const int I = (s * t) % SDIM;
                Ar += zr[I] * x0[t].x - zi[I] * x0[t].y;
                Ai += zr[I] * x0[t].y + zi[I] * x0[t].x;
            }
            sT10[ts][s] = make_float2(Ar, Ai);
        }
    }
    __syncthreads();

    // ---- Phase B: stage 2 (s-split; twiddles by recurrence) ----
    float Ereg[SDIM], Dreg[2][SDIM];
    float Ereg2[SDIM];
    if (!isV0) {
        // u1 = F[1][c], r = sqrt(33)*u1 (unit rotation e^{-2pi i c/33})
        const float2 u1a = make_float2(fwr[WDIM + c1], fwi[WDIM + c1]);
        const float2 u1b = make_float2(fwr[WDIM + c2], fwi[WDIM + c2]);
        const float2 ra = make_float2(u1a.x * invk, u1a.y * invk);
        const float2 rb = make_float2(u1b.x * invk, u1b.y * invk);
        #pragma unroll
        for (int g = 0; g < 2; g++) {
            const int s0 = g ? 3 : 0;
            const int ns = g ? 2 : 3;
            float Xr[4][3], Xi[4][3];
            #pragma unroll
            for (int ss = 0; ss < 3; ss++) {
                if (ss < ns) {
                    const float2 t10 = sT10[ts][s0 + ss];
                    const float br = k * t10.x, bi = k * t10.y;
                    #pragma unroll
                    for (int c = 0; c < 4; c++) { Xr[c][ss] = br; Xi[c][ss] = bi; }
                }
            }
            float2 fa = u1a, fb = u1b;
            #pragma unroll 4
            for (int w = 0; w < NPAIR; w++) {
                #pragma unroll
                for (int ss = 0; ss < 3; ss++) {
                    if (ss < ns) {
                        const float4 sd = sSD[(ts * NPAIR + w) * SDIM + s0 + ss];
                        {
                            const float pa = fa.x * sd.x, pb = fa.y * sd.w;
                            const float pc_ = fa.x * sd.y, pd = fa.y * sd.z;
                            Xr[0][ss] += pa - pb;  Xi[0][ss] += pc_ + pd;
                            Xr[1][ss] += pa + pb;  Xi[1][ss] += pc_ - pd;
                        }
                        {
                            const float pa = fb.x * sd.x, pb = fb.y * sd.w;
                            const float pc_ = fb.x * sd.y, pd = fb.y * sd.z;
                            Xr[2][ss] += pa - pb;  Xi[2][ss] += pc_ + pd;
                            Xr[3][ss] += pa + pb;  Xi[3][ss] += pc_ - pd;
                        }
                    }
                }
                const float2 na = make_float2(fa.x * ra.x - fa.y * ra.y,
                                              fa.x * ra.y + fa.y * ra.x);
                const float2 nb = make_float2(fb.x * rb.x - fb.y * rb.y,
                                              fb.x * rb.y + fb.y * rb.x);
                fa = na; fb = nb;
            }
            #pragma unroll
            for (int ss = 0; ss < 3; ss++) {
                if (ss < ns) {
                    const int s = s0 + ss;
                    const float Pv0 = Xr[0][ss]*Xr[0][ss] + Xi[0][ss]*Xi[0][ss];
                    const float Pm0 = Xr[1][ss]*Xr[1][ss] + Xi[1][ss]*Xi[1][ss];
                    const float Pv1 = Xr[2][ss]*Xr[2][ss] + Xi[2][ss]*Xi[2][ss];
                    const float Pm1 = Xr[3][ss]*Xr[3][ss] + Xi[3][ss]*Xi[3][ss];
                    Ereg[s]  = Pv0 + Pm0;  Dreg[0][s] = Pv0 - Pm0;
                    Ereg2[s] = Pv1 + Pm1;  Dreg[1][s] = Pv1 - Pm1;
                }
            }
        }
    } else {
        float sr[SDIM] = {0,0,0,0,0}, sm[SDIM] = {0,0,0,0,0};
        #pragma unroll 4
        for (int w = 0; w < NPAIR; w++) {
            #pragma unroll
            for (int s = 0; s < SDIM; s++) {
                const float2 sv = *reinterpret_cast<const float2*>(
                    &sSD[(ts * NPAIR + w) * SDIM + s]);
                sr[s] += sv.x;  sm[s] += sv.y;
            }
        }
        #pragma unroll
        for (int s = 0; s < SDIM; s++) {
            const float X0r = k * (sT10[ts][s].x + sr[s]);
            const float X0i = k * (sT10[ts][s].y + sm[s]);
            sP0[ts][s] = X0r * X0r + X0i * X0i;
        }
    }
    __syncthreads();                             // all sSD reads complete

    // ---- Phase C: publish E/D into union region ----
    if (!isV0) {
        const int i0 = ts * NPAIR + 2 * j;
        sEDa[i0]     = make_float4(Ereg[0],  Ereg[1],  Ereg[2],  Ereg[3]);
        sEDb[i0]     = make_float4(Dreg[0][0], Dreg[0][1], Dreg[0][2], Dreg[0][3]);
        sEDc[i0]     = make_float2(Ereg[4],  Dreg[0][4]);
        sEDa[i0 + 1] = make_float4(Ereg2[0], Ereg2[1], Ereg2[2], Ereg2[3]);
        sEDb[i0 + 1] = make_float4(Dreg[1][0], Dreg[1][1], Dreg[1][2], Dreg[1][3]);
        sEDc[i0 + 1] = make_float2(Ereg2[4], Dreg[1][4]);
    }
    __syncthreads();

    // ---- Phase D: stages 3 + 4 (twiddles by recurrence) ----
    if (!isV0) {
        const float2 u1a = make_float2(fwr[WDIM + c1], fwi[WDIM + c1]);
        const float2 u1b = make_float2(fwr[WDIM + c2], fwi[WDIM + c2]);
        const float2 ra = make_float2(u1a.x * invk, u1a.y * invk);
        const float2 rb = make_float2(u1b.x * invk, u1b.y * invk);
        float t2r[2][SDIM], t2i[2][SDIM];
        #pragma unroll
        for (int s = 0; s < SDIM; s++) {
            const float b = k * sP0[ts][s];
            t2r[0][s] = b; t2r[1][s] = b;
            t2i[0][s] = 0.f; t2i[1][s] = 0.f;
        }
        float2 fa = u1a, fb = u1b;
        #pragma unroll 4
        for (int w = 0; w < NPAIR; w++) {
            const float4 Ea = sEDa[ts * NPAIR + w];
            const float4 Db = sEDb[ts * NPAIR + w];
            const float2 ec = sEDc[ts * NPAIR + w];
            t2r[0][0] += Ea.x * fa.x;  t2i[0][0] -= Db.x * fa.y;
            t2r[0][1] += Ea.y * fa.x;  t2i[0][1] -= Db.y * fa.y;
            t2r[0][2] += Ea.z * fa.x;  t2i[0][2] -= Db.z * fa.y;
            t2r[0][3] += Ea.w * fa.x;  t2i[0][3] -= Db.w * fa.y;
            t2r[0][4] += ec.x * fa.x;  t2i[0][4] -= ec.y * fa.y;
            t2r[1][0] += Ea.x * fb.x;  t2i[1][0] -= Db.x * fb.y;
            t2r[1][1] += Ea.y * fb.x;  t2i[1][1] -= Db.y * fb.y;
            t2r[1][2] += Ea.z * fb.x;  t2i[1][2] -= Db.z * fb.y;
            t2r[1][3] += Ea.w * fb.x;  t2i[1][3] -= Db.w * fb.y;
            t2r[1][4] += ec.x * fb.x;  t2i[1][4] -= ec.y * fb.y;
            const float2 na = make_float2(fa.x * ra.x - fa.y * ra.y,
                                          fa.x * ra.y + fa.y * ra.x);
            const float2 nb = make_float2(fb.x * rb.x - fb.y * rb.y,
                                          fb.x * rb.y + fb.y * rb.x);
            fa = na; fb = nb;
        }
        #pragma unroll
        for (int pc = 0; pc < 2; pc++) {
            const int v = 2 * j + 1 + pc;
            #pragma unroll
            for (int sp = 0; sp < SDIM; sp++) {
                float yr = 0.f, yi = 0.f;
                #pragma unroll
                for (int s = 0; s < SDIM; s++) {
                    const int I = (s * sp) % SDIM;
                    yr += zr[I] * t2r[pc][s] + zi[I] * t2i[pc][s];
                    yi += zr[I] * t2i[pc][s] - zi[I] * t2r[pc][s];
                }
                unsigned int oidx = (((unsigned int)n * SDIM + sp) * ADIM + a) * WDIM + v;
                const int sp2 = (SDIM - sp) % SDIM;
                unsigned int midx = (((unsigned int)n * SDIM + sp2) * ADIM + a) * WDIM + (WDIM - v);
                if (real_only) {
                    if (oidx < out_limit) outf[oidx] = yr;
                    if (midx < out_limit) outf[midx] = yr;
                } else {
                    if (2u * oidx + 1u < out_limit)
                        reinterpret_cast<float2*>(outf)[oidx] = make_float2(yr, yi);
                    if (2u * midx + 1u < out_limit)
                        reinterpret_cast<float2*>(outf)[midx] = make_float2(yr, -yi);
                }
            }
        }
    } else {
        float accE[SDIM] = {0,0,0,0,0};
        #pragma unroll 4
        for (int w = 0; w < NPAIR; w++) {
            const float4 Ea = sEDa[ts * NPAIR + w];
            const float2 ec = sEDc[ts * NPAIR + w];
            accE[0] += Ea.x; accE[1] += Ea.y; accE[2] += Ea.z; accE[3] += Ea.w;
            accE[4] += ec.x;
        }
        float t2r0[SDIM];
        #pragma unroll
        for (int s = 0; s < SDIM; s++)
            t2r0[s] = k * (sP0[ts][s] + accE[s]);
        #pragma unroll
        for (int sp = 0; sp < SDIM; sp++) {
            float yr = 0.f, yi = 0.f;
            #pragma unroll
            for (int s = 0; s < SDIM; s++) {
                const int I = (s * sp) % SDIM;
                yr += zr[I] * t2r0[s];
                yi -= zi[I] * t2r0[s];
            }
            unsigned int oidx = (((unsigned int)n * SDIM + sp) * ADIM + a) * WDIM;
            if (real_only) {
                if (oidx < out_limit) outf[oidx] = yr;
            } else {
                if (2u * oidx + 1u < out_limit)
                    reinterpret_cast<float2*>(outf)[oidx] = make_float2(yr, yi);
            }
        }
    }
}

extern "C" void kernel_launch(void* const* d_in, const int* in_sizes, int n_in,
                              void* d_out, int out_size)
{
    long long big_raw = -1;
    for (int i = 0; i < n_in; i++)
        if ((long long)in_sizes[i] > big_raw) big_raw = in_sizes[i];

    const float *xr = 0, *xi = 0, *fsA = 0, *fsB = 0, *fwA = 0, *fwB = 0;
    int nsym = 0, nsub = 0, nbig = 0;
    for (int i = 0; i < n_in; i++) {
        const float* p = (const float*)d_in[i];
        long long c = in_sizes[i];
        if (c == SDIM * SDIM) {
            if (nsym++ == 0) fsA = p; else if (!fsB) fsB = p;
        } else if (c == WDIM * WDIM) {
            if (nsub++ == 0) fwA = p; else if (!fwB) fwB = p;
        } else if (c == big_raw) {
            if (nbig++ == 0) xr = p; else if (!xi) xi = p;
        }
    }
    if (!xr || !xi || !fsA || !fsB || !fwA || !fwB) return;

    const long long C = big_raw;
    const int N = (int)(C / (SDIM * ADIM * WDIM));
    const int total_tiles = N * ADIM;
    if (total_tiles <= 0) return;
    const int blocks = (total_tiles + TPB - 1) / TPB;

    const int real_only = ((long long)out_size >= 2 * C) ? 0 : 1;

    autocorr_kernel<<<blocks, THREADS>>>(
        xr, xi, fsA, fsB, fwA, fwB, (float*)d_out, total_tiles,
        (unsigned int)C, (unsigned int)out_size, real_only);
}